// round 8
// baseline (speedup 1.0000x reference)
#include <cuda_runtime.h>

// Fused persistent LSTM + MLP classifier, v5 (resubmit: R7 died in GPU-broker
// container acquisition before compile; no kernel-side evidence exists).
// R6: two-half pipeline works (801us, fma 53.6%) but 2 warps/SMSP leave
// ~40% of each phase stalled (1537 cyc/phase vs 912 FFMA2 floor).
// v5: NT=512 (4 warps/SMSP) via 4-way K split (KH=29, K zero-padded to 116),
// 2 gates x 29 k weights in regs (~95 regs, under the 128 cap @ 512 thr).
// Same phase structure: phase p = GEMM(half g=p&1, t=p>>1) || cell(half 1-g).

namespace {

constexpr int Bn   = 1024;
constexpr int Sn   = 512;
constexpr int In   = 50;
constexpr int Hn   = 64;
constexpr int F1n  = 32;
constexpr int Cn   = 2;
constexpr int KTOT = 114;        // 64 + 50
constexpr int KPAD = 116;        // zero-padded so 4*29 splits evenly
constexpr int KH   = 29;         // K quarter per thread
constexpr int TB   = 8;          // rows per block (two halves of 4)
constexpr int GRID = Bn / TB;    // 128
constexpr int NT   = 512;

struct Smem {
  float act[2][KPAD][4];            // [half][k][row-in-half]      3712 B
  unsigned long long part[2][4][2][128][2];
  // [half][kq][rowpair][gatepair][gate-in-pair] packed {row even,row odd}
  //                                                              32768 B
  float f1[TB][F1n];                //                              1024 B
};

using u64 = unsigned long long;

__device__ __forceinline__ u64 pack2(float lo, float hi) {
  u64 r;
  asm("mov.b64 %0, {%1, %2};" : "=l"(r)
      : "r"(__float_as_uint(lo)), "r"(__float_as_uint(hi)));
  return r;
}
__device__ __forceinline__ void unpack2(u64 v, float& lo, float& hi) {
  unsigned a, b;
  asm("mov.b64 {%0, %1}, %2;" : "=r"(a), "=r"(b) : "l"(v));
  lo = __uint_as_float(a);
  hi = __uint_as_float(b);
}
__device__ __forceinline__ u64 fma2(u64 a, u64 b, u64 c) {
  u64 d;
  asm("fma.rn.f32x2 %0, %1, %2, %3;" : "=l"(d) : "l"(a), "l"(b), "l"(c));
  return d;
}
__device__ __forceinline__ u64 add2(u64 a, u64 b) {
  u64 d;
  asm("add.rn.f32x2 %0, %1, %2;" : "=l"(d) : "l"(a), "l"(b));
  return d;
}
__device__ __forceinline__ float tanh_ap(float x) {
  float y;
  asm("tanh.approx.f32 %0, %1;" : "=f"(y) : "f"(x));
  return y;
}
__device__ __forceinline__ float sigmoid_ap(float x) {
  return fmaf(0.5f, tanh_ap(0.5f * x), 0.5f);
}

__global__ __launch_bounds__(NT, 1) void lstm_fused(
    const float* __restrict__ x,
    const float* __restrict__ W_ih, const float* __restrict__ W_hh,
    const float* __restrict__ b_ih, const float* __restrict__ b_hh,
    const float* __restrict__ W1,   const float* __restrict__ b1,
    const float* __restrict__ W2,   const float* __restrict__ b2,
    float* __restrict__ out) {
  __shared__ Smem s;

  const int tid  = threadIdx.x;
  const int row0 = blockIdx.x * TB;

  // ---- GEMM role: gates 2gp,2gp+1 x K quarter kq ----
  const int gp = tid & 127;
  const int kq = tid >> 7;          // 0..3
  const int k0 = kq * KH;

  float wr0[KH], wr1[KH];
  {
    const int g0 = 2 * gp, g1 = 2 * gp + 1;
#pragma unroll
    for (int j = 0; j < KH; j++) {
      const int k = k0 + j;
      float a = 0.0f, b = 0.0f;
      if (k < Hn) {
        a = W_hh[g0 * Hn + k];
        b = W_hh[g1 * Hn + k];
      } else if (k < KTOT) {
        a = W_ih[g0 * In + (k - Hn)];
        b = W_ih[g1 * In + (k - Hn)];
      }
      wr0[j] = a;
      wr1[j] = b;
    }
  }
  u64 bias2[2];
  {
    const float bb0 = (kq == 0) ? b_ih[2 * gp] + b_hh[2 * gp] : 0.0f;
    const float bb1 = (kq == 0) ? b_ih[2 * gp + 1] + b_hh[2 * gp + 1] : 0.0f;
    bias2[0] = pack2(bb0, bb0);
    bias2[1] = pack2(bb1, bb1);
  }

  // ---- cell role (tid < 256): unit cu, rowpair crp, half chf ----
  const int cu   = tid & 63;
  const int crp  = (tid >> 6) & 1;
  const int chf  = tid >> 7;        // valid as half id only when tid<256
  const bool is_cell = (tid < 256);
  u64 c2 = 0ull;

  // ---- x-prefetch role: 400 slots, 1 per thread ----
  const bool xok = (tid < TB * In);
  int xi = 0, xrl = 0, xh = 0;
  const float* xptr = x;
  if (xok) {
    const int r = tid / In;
    xi  = tid - r * In;
    xh  = r >> 2;
    xrl = r & 3;
    xptr = x + (long)(row0 + r) * (Sn * In) + xi;
  }

  // ---- init: zero act (incl. K pad rows), then x_t0 ----
  for (int idx = tid; idx < 2 * KPAD * 4; idx += NT)
    (&s.act[0][0][0])[idx] = 0.0f;
  __syncthreads();
  if (xok) s.act[xh][Hn + xi][xrl] = xptr[0];
  __syncthreads();

  float xp = 0.0f;
  bool  pend = false;

  for (int p = 0; p <= 2 * Sn; p++) {
    const int  g       = p & 1;       // GEMM half this phase
    const int  t       = p >> 1;      // GEMM step
    const bool do_gemm = (p < 2 * Sn);

    // 1) x LDG for half g, step t+1 (latency-first)
    if (do_gemm && xok && g == xh && (t + 1 < Sn)) {
      xp = xptr[(t + 1) * In];
      pend = true;
    }

    // 2) cell for half c = 1-g (gates produced last phase)
    const int c = 1 - g;
    if (p >= 1 && is_cell && chf == c) {
      u64 gs[4];
#pragma unroll
      for (int q = 0; q < 4; q++) {
        const int gg = cu + Hn * q;
        u64 sum = add2(s.part[c][0][crp][gg >> 1][gg & 1],
                       s.part[c][1][crp][gg >> 1][gg & 1]);
        sum = add2(sum, s.part[c][2][crp][gg >> 1][gg & 1]);
        gs[q] = add2(sum, s.part[c][3][crp][gg >> 1][gg & 1]);
      }
      float i0, i1, f0, f1, g0, g1, o0, o1, ca, cb;
      unpack2(gs[0], i0, i1);
      unpack2(gs[1], f0, f1);
      unpack2(gs[2], g0, g1);
      unpack2(gs[3], o0, o1);
      unpack2(c2, ca, cb);
      i0 = sigmoid_ap(i0); i1 = sigmoid_ap(i1);
      f0 = sigmoid_ap(f0); f1 = sigmoid_ap(f1);
      g0 = tanh_ap(g0);    g1 = tanh_ap(g1);
      o0 = sigmoid_ap(o0); o1 = sigmoid_ap(o1);
      ca = fmaf(f0, ca, i0 * g0);
      cb = fmaf(f1, cb, i1 * g1);
      c2 = pack2(ca, cb);
      *reinterpret_cast<float2*>(&s.act[c][cu][2 * crp]) =
          make_float2(o0 * tanh_ap(ca), o1 * tanh_ap(cb));
    }

    // 3) GEMM half g, step t: 2 gates x 4 rows over K quarter (all threads)
    if (do_gemm) {
      u64 acc00 = bias2[0], acc01 = bias2[1];  // rowpair 0 (rows 0,1)
      u64 acc10 = bias2[0], acc11 = bias2[1];  // rowpair 1 (rows 2,3)
#pragma unroll
      for (int j = 0; j < KH; j++) {
        const int k = k0 + j;
        const ulonglong2 aa =
            *reinterpret_cast<const ulonglong2*>(&s.act[g][k][0]);
        const u64 w0 = pack2(wr0[j], wr0[j]);
        const u64 w1 = pack2(wr1[j], wr1[j]);
        acc00 = fma2(aa.x, w0, acc00);
        acc01 = fma2(aa.x, w1, acc01);
        acc10 = fma2(aa.y, w0, acc10);
        acc11 = fma2(aa.y, w1, acc11);
      }
      {
        ulonglong2 v;
        v.x = acc00; v.y = acc01;
        *reinterpret_cast<ulonglong2*>(&s.part[g][kq][0][gp][0]) = v;
        v.x = acc10; v.y = acc11;
        *reinterpret_cast<ulonglong2*>(&s.part[g][kq][1][gp][0]) = v;
      }
    }

    // 4) commit pending x for half 1-g (act[1-g] not GEMM-read this phase)
    if (pend && xh == 1 - g) {
      s.act[xh][Hn + xi][xrl] = xp;
      pend = false;
    }

    __syncthreads();
  }

  // ---- classifier head: h_last in act[row>>2][u][row&3] ----
  if (tid < TB * F1n) {
    const int row = tid >> 5;
    const int f   = tid & 31;
    float a1 = b1[f];
#pragma unroll
    for (int u = 0; u < Hn; u++)
      a1 = fmaf(s.act[row >> 2][u][row & 3], W1[f * Hn + u], a1);
    s.f1[row][f] = fmaxf(a1, 0.0f);
  }
  __syncthreads();
  if (tid < TB * Cn) {
    const int row = tid >> 1;
    const int cl  = tid & 1;
    float o = b2[cl];
#pragma unroll
    for (int f = 0; f < F1n; f++) o = fmaf(s.f1[row][f], W2[cl * F1n + f], o);
    out[(row0 + row) * Cn + cl] = o;
  }
}

}  // namespace

extern "C" void kernel_launch(void* const* d_in, const int* in_sizes, int n_in,
                              void* d_out, int out_size) {
  (void)in_sizes; (void)n_in; (void)out_size;
  const float* x    = (const float*)d_in[0];
  const float* W_ih = (const float*)d_in[1];
  const float* W_hh = (const float*)d_in[2];
  const float* b_ih = (const float*)d_in[3];
  const float* b_hh = (const float*)d_in[4];
  const float* W1   = (const float*)d_in[5];
  const float* b1   = (const float*)d_in[6];
  const float* W2   = (const float*)d_in[7];
  const float* b2   = (const float*)d_in[8];
  float* out = (float*)d_out;

  lstm_fused<<<GRID, NT>>>(x, W_ih, W_hh, b_ih, b_hh, W1, b1, W2, b2, out);
}